// round 14
// baseline (speedup 1.0000x reference)
#include <cuda_runtime.h>
#include <cstdint>
#include <cstddef>

#define TSTEPS 512
#define BATCH  128

// 192MB scratch for the input projection (static device array: allowed).
__device__ float g_Gx[(size_t)BATCH * TSTEPS * 768];

// ---- f32x2 helpers ----
typedef unsigned long long ull;
__device__ __forceinline__ ull pack2(float x, float y) {
    ull u; asm("mov.b64 %0, {%1,%2};" : "=l"(u) : "f"(x), "f"(y)); return u;
}
__device__ __forceinline__ void unpack2(ull u, float& x, float& y) {
    asm("mov.b64 {%0,%1}, %2;" : "=f"(x), "=f"(y) : "l"(u));
}
__device__ __forceinline__ void fma2(ull& d, ull a, ull b) {
    asm("fma.rn.f32x2 %0, %1, %2, %0;" : "+l"(d) : "l"(a), "l"(b));
}

// ---- cluster helpers ----
__device__ __forceinline__ uint32_t smem_u32(const void* p) {
    uint32_t a;
    asm("{ .reg .u64 t; cvta.to.shared.u64 t, %1; cvt.u32.u64 %0, t; }" : "=r"(a) : "l"(p));
    return a;
}
__device__ __forceinline__ uint32_t mapa_rank(uint32_t addr, uint32_t rank) {
    uint32_t r; asm("mapa.shared::cluster.u32 %0, %1, %2;" : "=r"(r) : "r"(addr), "r"(rank));
    return r;
}
__device__ __forceinline__ void st_cluster_u64(uint32_t addr, ull v) {
    asm volatile("st.shared::cluster.b64 [%0], %1;" :: "r"(addr), "l"(v));
}
__device__ __forceinline__ void cluster_arrive() {
    asm volatile("barrier.cluster.arrive.aligned;" ::: "memory");
}
__device__ __forceinline__ void cluster_wait() {
    asm volatile("barrier.cluster.wait.aligned;" ::: "memory");
}
__device__ __forceinline__ void cluster_sync() {
    cluster_arrive(); cluster_wait();
}
__device__ __forceinline__ uint32_t cluster_rank() {
    uint32_t r; asm("mov.u32 %0, %%cluster_ctarank;" : "=r"(r)); return r;
}

// fast activations
__device__ __forceinline__ float fast_sigmoid(float x) {
    return __fdividef(1.0f, 1.0f + __expf(-x));
}
__device__ __forceinline__ float fast_tanh(float x) {
    return 2.0f * __fdividef(1.0f, 1.0f + __expf(-2.0f * x)) - 1.0f;
}

// butterfly reduce a (lo,hi) pair over the kg dimension (lane bits 2,3,4)
__device__ __forceinline__ void bfly_kg(float& lo, float& hi) {
    lo += __shfl_xor_sync(0xffffffffu, lo, 4);
    hi += __shfl_xor_sync(0xffffffffu, hi, 4);
    lo += __shfl_xor_sync(0xffffffffu, lo, 8);
    hi += __shfl_xor_sync(0xffffffffu, hi, 8);
    lo += __shfl_xor_sync(0xffffffffu, lo, 16);
    hi += __shfl_xor_sync(0xffffffffu, hi, 16);
}

// ============================================================================
// Stage 1: Gx[m][gate*256+n] = x[m] @ W[:256] + b.  BM=128 BN=64 BK=32.
// Single-buffer tiles (latency not the binder), W pre-packed (w,w) in SMEM,
// A and W read via LDS.128: inner iter = 4 LDS + 16 fma2 (80% FMA density).
// ============================================================================
// layout: As[32][132] floats (16.5KB), Wsp[32][64] ulls (16KB)
#define PROJ_SMEM_BYTES (32 * 132 * 4 + 32 * 64 * 8)

__global__ __launch_bounds__(256) void proj_kernel(
    const float* __restrict__ x,
    const float* __restrict__ Wr, const float* __restrict__ br,
    const float* __restrict__ Wz, const float* __restrict__ bz,
    const float* __restrict__ Wc, const float* __restrict__ bc)
{
    extern __shared__ char psm[];
    float (*As)[132] = reinterpret_cast<float (*)[132]>(psm);
    ull   (*Wsp)[64] = reinterpret_cast<ull (*)[64]>(psm + 32 * 132 * 4);

    const int mTile = blockIdx.x, nTile = blockIdx.y;
    const int gate = nTile >> 2, nGateBase = (nTile & 3) * 64;
    const float* W    = (gate == 0) ? Wr : ((gate == 1) ? Wz : Wc);
    const float* bias = (gate == 0) ? br : ((gate == 1) ? bz : bc);

    const int tid = threadIdx.x;
    const int tx = tid & 15, ty = tid >> 4;
    const int mBase = mTile * 128;

    ull acc[4][4];
    #pragma unroll
    for (int i = 0; i < 4; i++)
        #pragma unroll
        for (int jj = 0; jj < 4; jj++) acc[i][jj] = 0ull;

    float bv[4];
    #pragma unroll
    for (int jj = 0; jj < 4; jj++) bv[jj] = bias[nGateBase + tx * 4 + jj];

    for (int k0 = 0; k0 < 256; k0 += 32) {
        __syncthreads();
        // A tile: 128 rows x 32 k = 1024 float4 slots
        #pragma unroll
        for (int q = 0; q < 4; q++) {
            int idx = tid + q * 256, row = idx >> 3, c4 = idx & 7;
            float4 v = *reinterpret_cast<const float4*>(
                &x[(size_t)(mBase + row) * 256 + k0 + c4 * 4]);
            As[c4 * 4 + 0][row] = v.x; As[c4 * 4 + 1][row] = v.y;
            As[c4 * 4 + 2][row] = v.z; As[c4 * 4 + 3][row] = v.w;
        }
        // W tile: 32 k x 64 n, stored pre-packed (w,w)
        #pragma unroll
        for (int q = 0; q < 2; q++) {
            int s = tid + q * 256;
            int k = s >> 4, n4 = (s & 15) * 4;
            float4 v = *reinterpret_cast<const float4*>(
                &W[(size_t)(k0 + k) * 256 + nGateBase + n4]);
            ulonglong2 p0; p0.x = pack2(v.x, v.x); p0.y = pack2(v.y, v.y);
            ulonglong2 p1; p1.x = pack2(v.z, v.z); p1.y = pack2(v.w, v.w);
            *reinterpret_cast<ulonglong2*>(&Wsp[k][n4])     = p0;
            *reinterpret_cast<ulonglong2*>(&Wsp[k][n4 + 2]) = p1;
        }
        __syncthreads();

        #pragma unroll
        for (int k = 0; k < 32; k++) {
            const ulonglong2* ap = reinterpret_cast<const ulonglong2*>(&As[k][ty * 8]);
            ulonglong2 aA = ap[0], aB = ap[1];
            const ulonglong2* wp = reinterpret_cast<const ulonglong2*>(&Wsp[k][tx * 4]);
            ulonglong2 w01 = wp[0], w23 = wp[1];
            fma2(acc[0][0], aA.x, w01.x); fma2(acc[1][0], aA.y, w01.x);
            fma2(acc[2][0], aB.x, w01.x); fma2(acc[3][0], aB.y, w01.x);
            fma2(acc[0][1], aA.x, w01.y); fma2(acc[1][1], aA.y, w01.y);
            fma2(acc[2][1], aB.x, w01.y); fma2(acc[3][1], aB.y, w01.y);
            fma2(acc[0][2], aA.x, w23.x); fma2(acc[1][2], aA.y, w23.x);
            fma2(acc[2][2], aB.x, w23.x); fma2(acc[3][2], aB.y, w23.x);
            fma2(acc[0][3], aA.x, w23.y); fma2(acc[1][3], aA.y, w23.y);
            fma2(acc[2][3], aB.x, w23.y); fma2(acc[3][3], aB.y, w23.y);
        }
    }

    const int nOut = gate * 256 + nGateBase + tx * 4;
    #pragma unroll
    for (int rp = 0; rp < 4; rp++) {
        float r0[4], r1[4];
        #pragma unroll
        for (int jj = 0; jj < 4; jj++) {
            unpack2(acc[rp][jj], r0[jj], r1[jj]);
            r0[jj] += bv[jj]; r1[jj] += bv[jj];
        }
        int m0 = mBase + ty * 8 + rp * 2;
        *reinterpret_cast<float4*>(&g_Gx[(size_t)m0 * 768 + nOut]) =
            make_float4(r0[0], r0[1], r0[2], r0[3]);
        *reinterpret_cast<float4*>(&g_Gx[(size_t)(m0 + 1) * 768 + nOut]) =
            make_float4(r1[0], r1[1], r1[2], r1[3]);
    }
}

// ============================================================================
// Stage 2: recurrence — R11 structure exactly; ONLY change: Wc pre-packed
// (w,w) as u64 in SMEM (drops 32 pack-MOVs per thread per step in GEMM_c).
// ============================================================================
struct __align__(16) RecSmem {
    ull   wc8[32][8][8][4];    // Wc h-part packed [kk][c>>2][kg][c&3]   64KB
    float hT[2][264 * 4];      // h, skewed rows of 16B [buf]           8.25KB
    float rhT[264 * 4];        // r*h, skewed                           4.1KB
};

__global__ __launch_bounds__(256, 2) __cluster_dims__(8, 1, 1)
void rec_kernel(const float* __restrict__ h0,
                const float* __restrict__ Wr,
                const float* __restrict__ Wz,
                const float* __restrict__ Wc,
                float* __restrict__ out)
{
    extern __shared__ char smem_raw[];
    RecSmem& S = *reinterpret_cast<RecSmem*>(smem_raw);

    const int tid = threadIdx.x;
    const int warp = tid >> 5, lane = tid & 31;
    const int j = (int)cluster_rank();       // 0..7
    const int b0 = (blockIdx.x >> 3) * 4;    // first batch row of cluster

    // roles
    const int c_local = warp * 4 + (lane & 3);   // output col within CTA, 0..31
    const int kg = lane >> 2;                    // split-K group, 0..7
    const int kb = kg * 32;
    const bool pusher = (lane < 16);
    const int rp = (lane >> 2) & 1;              // row-pair (pushers)
    const int pg = (lane >> 3) & 1;              // peer group (pushers)
    const int k_glob = j * 32 + c_local;
    const int kr_own = k_glob + j;               // skewed row of own col

    // ---- register weights for r and z gates (1 col x 32 k each) ----
    float w1r[32], w1z[32];
    {
        const int c = k_glob;
        #pragma unroll
        for (int kk = 0; kk < 32; kk++) {
            w1r[kk] = Wr[(size_t)(256 + kb + kk) * 256 + c];
            w1z[kk] = Wz[(size_t)(256 + kb + kk) * 256 + c];
        }
    }

    // ---- SMEM init: packed Wc tile (bank-friendly layout), h buffer 0 ----
    for (int idx = tid; idx < 8192; idx += 256) {
        int k = idx >> 5, c = idx & 31;
        float w = Wc[(size_t)(256 + k) * 256 + j * 32 + c];
        S.wc8[k & 31][c >> 2][k >> 5][c & 3] = pack2(w, w);
    }
    for (int idx = tid; idx < 1024; idx += 256) {
        int k = idx >> 2, r = idx & 3;
        S.hT[0][(k + (k >> 5)) * 4 + r] = h0[(size_t)(b0 + r) * 256 + k];
    }
    __syncthreads();
    cluster_sync();   // peers' hT init visible before any remote op

    // ---- peer DSMEM addresses ----
    const uint32_t base = smem_u32(&S);
    uint32_t peer[8];
    #pragma unroll
    for (int rk = 0; rk < 8; rk++) peer[rk] = mapa_rank(base, (uint32_t)rk);
    const uint32_t off_h[2]  = { (uint32_t)(smem_u32(&S.hT[0][0]) - base),
                                 (uint32_t)(smem_u32(&S.hT[1][0]) - base) };
    const uint32_t off_rh    = (uint32_t)(smem_u32(&S.rhT[0]) - base);

    // ---- Gx address bases for pusher lanes ----
    const size_t bR0 = (size_t)(b0 + 2 * rp)     * TSTEPS * 768 + k_glob;
    const size_t bR1 = (size_t)(b0 + 2 * rp + 1) * TSTEPS * 768 + k_glob;

    // prologue: gR for step 0
    float gR0 = 0.f, gR1 = 0.f;
    if (pusher) { gR0 = g_Gx[bR0]; gR1 = g_Gx[bR1]; }

    #pragma unroll 1
    for (int t = 0; t < TSTEPS; t++) {
        const int buf = t & 1;

        // gZ/gC loads first: latency overlaps WAIT2 + GEMM_r..GEMM_z
        float gZ0 = 0.f, gZ1 = 0.f, gC0 = 0.f, gC1 = 0.f;
        if (pusher) {
            const size_t to = (size_t)t * 768;
            gZ0 = g_Gx[bR0 + to + 256]; gZ1 = g_Gx[bR1 + to + 256];
            gC0 = g_Gx[bR0 + to + 512]; gC1 = g_Gx[bR1 + to + 512];
        }

        // WAIT2: h(t) pushed by all peers at end of step t-1
        if (t > 0) cluster_wait();

        // -- GEMM_r: h @ Wh_r (skewed hT; per-iter row kb+kk+kg) --
        float r0l, r0h, r1l, r1h;
        {
            ull a0 = 0, a1 = 0;
            #pragma unroll
            for (int kk = 0; kk < 32; kk++) {
                ulonglong2 hp = *reinterpret_cast<const ulonglong2*>(
                    &S.hT[buf][(kb + kk + kg) * 4]);
                ull w2 = pack2(w1r[kk], w1r[kk]);
                fma2(a0, hp.x, w2); fma2(a1, hp.y, w2);
            }
            unpack2(a0, r0l, r0h); unpack2(a1, r1l, r1h);
            bfly_kg(r0l, r0h); bfly_kg(r1l, r1h);
        }

        // -- epi_r (pushers): sigmoid r, push r*h (4 peers each) --
        if (pusher) {
            float sl = rp ? r1l : r0l, sh = rp ? r1h : r0h;
            float v0 = fast_sigmoid(sl + gR0), v1 = fast_sigmoid(sh + gR1);
            ull h2 = *reinterpret_cast<const ull*>(&S.hT[buf][kr_own * 4 + 2 * rp]);
            float ha, hb; unpack2(h2, ha, hb);
            ull rh2 = pack2(v0 * ha, v1 * hb);
            uint32_t o = off_rh + (uint32_t)((kr_own * 4 + 2 * rp) * 4);
            #pragma unroll
            for (int p = 0; p < 4; p++) st_cluster_u64(peer[4 * pg + p] + o, rh2);
        }
        // ARRIVE1: rh pushes issued (release); propagation hides under GEMM_z
        cluster_arrive();

        // -- GEMM_z: h @ Wh_z (overlaps the r*h exchange + barrier) --
        float z0 = 0.f, z1 = 0.f;
        {
            ull a0 = 0, a1 = 0;
            #pragma unroll
            for (int kk = 0; kk < 32; kk++) {
                ulonglong2 hp = *reinterpret_cast<const ulonglong2*>(
                    &S.hT[buf][(kb + kk + kg) * 4]);
                ull w2 = pack2(w1z[kk], w1z[kk]);
                fma2(a0, hp.x, w2); fma2(a1, hp.y, w2);
            }
            float z0l, z0h, z1l, z1h;
            unpack2(a0, z0l, z0h); unpack2(a1, z1l, z1h);
            bfly_kg(z0l, z0h); bfly_kg(z1l, z1h);
            if (pusher) {   // z stays in registers until epi_c (same lane)
                float sl = rp ? z1l : z0l, sh = rp ? z1h : z0h;
                z0 = fast_sigmoid(sl + gZ0); z1 = fast_sigmoid(sh + gZ1);
            }
        }

        // issue gR(t+1) prefetch BEFORE the wait: in flight across WAIT1+GEMM_c
        float gRn0 = gR0, gRn1 = gR1;
        if (pusher) {
            const size_t tn = (size_t)((t + 1 < TSTEPS) ? t + 1 : t) * 768;
            gRn0 = g_Gx[bR0 + tn]; gRn1 = g_Gx[bR1 + tn];
        }

        // WAIT1: rhT complete from all peers (mostly satisfied already)
        cluster_wait();

        // -- GEMM_c: (r*h) @ Wh_c (pre-packed Wc from SMEM: no pack MOVs) --
        float c0l, c0h, c1l, c1h;
        {
            ull a0 = 0, a1 = 0;
            #pragma unroll
            for (int kk = 0; kk < 32; kk++) {
                ulonglong2 hp = *reinterpret_cast<const ulonglong2*>(
                    &S.rhT[(kb + kk + kg) * 4]);
                ull w2 = S.wc8[kk][c_local >> 2][kg][c_local & 3];
                fma2(a0, hp.x, w2); fma2(a1, hp.y, w2);
            }
            unpack2(a0, c0l, c0h); unpack2(a1, c1l, c1h);
            bfly_kg(c0l, c0h); bfly_kg(c1l, c1h);
        }

        // -- epi_c (pushers): candidate, h update, output, push h(t+1) --
        if (pusher) {
            float sl = rp ? c1l : c0l, sh = rp ? c1h : c0h;
            float cv0 = fast_tanh(sl + gC0), cv1 = fast_tanh(sh + gC1);
            ull h2 = *reinterpret_cast<const ull*>(&S.hT[buf][kr_own * 4 + 2 * rp]);
            float ha, hb; unpack2(h2, ha, hb);
            float hn0 = ha + z0 * (cv0 - ha);
            float hn1 = hb + z1 * (cv1 - hb);
            if (pg == 0) {
                out[((size_t)(b0 + 2 * rp) * TSTEPS + t) * 256 + k_glob] = hn0;
                out[((size_t)(b0 + 2 * rp + 1) * TSTEPS + t) * 256 + k_glob] = hn1;
            }
            ull hn2 = pack2(hn0, hn1);
            uint32_t o = off_h[buf ^ 1] + (uint32_t)((kr_own * 4 + 2 * rp) * 4);
            #pragma unroll
            for (int p = 0; p < 4; p++) st_cluster_u64(peer[4 * pg + p] + o, hn2);
        }
        // ARRIVE2: h(t+1) pushes issued; next iteration's wait consumes it
        cluster_arrive();

        gR0 = gRn0; gR1 = gRn1;
    }

    // consume the final ARRIVE2 so no CTA exits with peer pushes in flight
    cluster_wait();
}

extern "C" void kernel_launch(void* const* d_in, const int* in_sizes, int n_in,
                              void* d_out, int out_size) {
    const float* x  = (const float*)d_in[0];
    const float* h0 = (const float*)d_in[1];
    const float* Wr = (const float*)d_in[2];
    const float* br = (const float*)d_in[3];
    const float* Wz = (const float*)d_in[4];
    const float* bz = (const float*)d_in[5];
    const float* Wc = (const float*)d_in[6];
    const float* bc = (const float*)d_in[7];
    float* out = (float*)d_out;

    cudaFuncSetAttribute(proj_kernel, cudaFuncAttributeMaxDynamicSharedMemorySize,
                         PROJ_SMEM_BYTES);
    cudaFuncSetAttribute(rec_kernel, cudaFuncAttributeMaxDynamicSharedMemorySize,
                         (int)sizeof(RecSmem));

    proj_kernel<<<dim3(512, 12), 256, PROJ_SMEM_BYTES>>>(x, Wr, br, Wz, bz, Wc, bc);
    rec_kernel<<<256, 256, sizeof(RecSmem)>>>(h0, Wr, Wz, Wc, out);
}

// round 15
// speedup vs baseline: 1.1554x; 1.1554x over previous
#include <cuda_runtime.h>
#include <cstdint>
#include <cstddef>

#define TSTEPS 512
#define BATCH  128

// 192MB scratch for the input projection (static device array: allowed).
__device__ float g_Gx[(size_t)BATCH * TSTEPS * 768];

// ---- f32x2 helpers ----
typedef unsigned long long ull;
__device__ __forceinline__ ull pack2(float x, float y) {
    ull u; asm("mov.b64 %0, {%1,%2};" : "=l"(u) : "f"(x), "f"(y)); return u;
}
__device__ __forceinline__ void unpack2(ull u, float& x, float& y) {
    asm("mov.b64 {%0,%1}, %2;" : "=f"(x), "=f"(y) : "l"(u));
}
__device__ __forceinline__ void fma2(ull& d, ull a, ull b) {
    asm("fma.rn.f32x2 %0, %1, %2, %0;" : "+l"(d) : "l"(a), "l"(b));
}

// ---- cluster helpers ----
__device__ __forceinline__ uint32_t smem_u32(const void* p) {
    uint32_t a;
    asm("{ .reg .u64 t; cvta.to.shared.u64 t, %1; cvt.u32.u64 %0, t; }" : "=r"(a) : "l"(p));
    return a;
}
__device__ __forceinline__ uint32_t mapa_rank(uint32_t addr, uint32_t rank) {
    uint32_t r; asm("mapa.shared::cluster.u32 %0, %1, %2;" : "=r"(r) : "r"(addr), "r"(rank));
    return r;
}
__device__ __forceinline__ void st_cluster_u64(uint32_t addr, ull v) {
    asm volatile("st.shared::cluster.b64 [%0], %1;" :: "r"(addr), "l"(v));
}
__device__ __forceinline__ void cluster_arrive() {
    asm volatile("barrier.cluster.arrive.aligned;" ::: "memory");
}
__device__ __forceinline__ void cluster_wait() {
    asm volatile("barrier.cluster.wait.aligned;" ::: "memory");
}
__device__ __forceinline__ void cluster_sync() {
    cluster_arrive(); cluster_wait();
}
__device__ __forceinline__ uint32_t cluster_rank() {
    uint32_t r; asm("mov.u32 %0, %%cluster_ctarank;" : "=r"(r)); return r;
}

// fast activations
__device__ __forceinline__ float fast_sigmoid(float x) {
    return __fdividef(1.0f, 1.0f + __expf(-x));
}
__device__ __forceinline__ float fast_tanh(float x) {
    return 2.0f * __fdividef(1.0f, 1.0f + __expf(-2.0f * x)) - 1.0f;
}

// butterfly reduce a (lo,hi) pair over the kg dimension (lane bits 2,3,4)
__device__ __forceinline__ void bfly_kg(float& lo, float& hi) {
    lo += __shfl_xor_sync(0xffffffffu, lo, 4);
    hi += __shfl_xor_sync(0xffffffffu, hi, 4);
    lo += __shfl_xor_sync(0xffffffffu, lo, 8);
    hi += __shfl_xor_sync(0xffffffffu, hi, 8);
    lo += __shfl_xor_sync(0xffffffffu, lo, 16);
    hi += __shfl_xor_sync(0xffffffffu, hi, 16);
}

// ============================================================================
// Stage 1: Gx[m][gate*256+n] = x[m] @ W[:256] + b.  BM=128 BN=64 BK=32.
// W pre-packed (w,w) in SMEM with CONFLICT-FREE layout Wsp2[q][k][txg]:
// inner-loop W loads are LDS.64 at 8B lane stride (one phase, no conflicts).
// Inner iter: 2 LDS.128 (A) + 4 LDS.64 (W) + 16 FFMA2, no pack MOVs.
// ============================================================================
// layout: As[32][132] floats (16.5KB), Wsp2[4][32][16] ulls (16KB)
#define PROJ_SMEM_BYTES (32 * 132 * 4 + 4 * 32 * 16 * 8)

__global__ __launch_bounds__(256) void proj_kernel(
    const float* __restrict__ x,
    const float* __restrict__ Wr, const float* __restrict__ br,
    const float* __restrict__ Wz, const float* __restrict__ bz,
    const float* __restrict__ Wc, const float* __restrict__ bc)
{
    extern __shared__ char psm[];
    float (*As)[132]    = reinterpret_cast<float (*)[132]>(psm);
    ull   (*Wsp2)[32][16] = reinterpret_cast<ull (*)[32][16]>(psm + 32 * 132 * 4);

    const int mTile = blockIdx.x, nTile = blockIdx.y;
    const int gate = nTile >> 2, nGateBase = (nTile & 3) * 64;
    const float* W    = (gate == 0) ? Wr : ((gate == 1) ? Wz : Wc);
    const float* bias = (gate == 0) ? br : ((gate == 1) ? bz : bc);

    const int tid = threadIdx.x;
    const int tx = tid & 15, ty = tid >> 4;
    const int mBase = mTile * 128;

    ull acc[4][4];
    #pragma unroll
    for (int i = 0; i < 4; i++)
        #pragma unroll
        for (int jj = 0; jj < 4; jj++) acc[i][jj] = 0ull;

    float bv[4];
    #pragma unroll
    for (int jj = 0; jj < 4; jj++) bv[jj] = bias[nGateBase + tx * 4 + jj];

    for (int k0 = 0; k0 < 256; k0 += 32) {
        __syncthreads();
        // A tile: 128 rows x 32 k = 1024 float4 slots
        #pragma unroll
        for (int q = 0; q < 4; q++) {
            int idx = tid + q * 256, row = idx >> 3, c4 = idx & 7;
            float4 v = *reinterpret_cast<const float4*>(
                &x[(size_t)(mBase + row) * 256 + k0 + c4 * 4]);
            As[c4 * 4 + 0][row] = v.x; As[c4 * 4 + 1][row] = v.y;
            As[c4 * 4 + 2][row] = v.z; As[c4 * 4 + 3][row] = v.w;
        }
        // W tile: 32 k x 64 n, stored packed into Wsp2[q][k][txg]
        #pragma unroll
        for (int q = 0; q < 2; q++) {
            int s = tid + q * 256;
            int k = s >> 4, txg = s & 15;
            float4 v = *reinterpret_cast<const float4*>(
                &W[(size_t)(k0 + k) * 256 + nGateBase + txg * 4]);
            Wsp2[0][k][txg] = pack2(v.x, v.x);
            Wsp2[1][k][txg] = pack2(v.y, v.y);
            Wsp2[2][k][txg] = pack2(v.z, v.z);
            Wsp2[3][k][txg] = pack2(v.w, v.w);
        }
        __syncthreads();

        #pragma unroll
        for (int k = 0; k < 32; k++) {
            const ulonglong2* ap = reinterpret_cast<const ulonglong2*>(&As[k][ty * 8]);
            ulonglong2 aA = ap[0], aB = ap[1];
            ull w0 = Wsp2[0][k][tx];
            ull w1 = Wsp2[1][k][tx];
            ull w2 = Wsp2[2][k][tx];
            ull w3 = Wsp2[3][k][tx];
            fma2(acc[0][0], aA.x, w0); fma2(acc[1][0], aA.y, w0);
            fma2(acc[2][0], aB.x, w0); fma2(acc[3][0], aB.y, w0);
            fma2(acc[0][1], aA.x, w1); fma2(acc[1][1], aA.y, w1);
            fma2(acc[2][1], aB.x, w1); fma2(acc[3][1], aB.y, w1);
            fma2(acc[0][2], aA.x, w2); fma2(acc[1][2], aA.y, w2);
            fma2(acc[2][2], aB.x, w2); fma2(acc[3][2], aB.y, w2);
            fma2(acc[0][3], aA.x, w3); fma2(acc[1][3], aA.y, w3);
            fma2(acc[2][3], aB.x, w3); fma2(acc[3][3], aB.y, w3);
        }
    }

    const int nOut = gate * 256 + nGateBase + tx * 4;
    #pragma unroll
    for (int rp = 0; rp < 4; rp++) {
        float r0[4], r1[4];
        #pragma unroll
        for (int jj = 0; jj < 4; jj++) {
            unpack2(acc[rp][jj], r0[jj], r1[jj]);
            r0[jj] += bv[jj]; r1[jj] += bv[jj];
        }
        int m0 = mBase + ty * 8 + rp * 2;
        *reinterpret_cast<float4*>(&g_Gx[(size_t)m0 * 768 + nOut]) =
            make_float4(r0[0], r0[1], r0[2], r0[3]);
        *reinterpret_cast<float4*>(&g_Gx[(size_t)(m0 + 1) * 768 + nOut]) =
            make_float4(r1[0], r1[1], r1[2], r1[3]);
    }
}

// ============================================================================
// Stage 2: recurrence — BYTE-IDENTICAL to R11/R13 (best: rec 2055us).
// 32 clusters x 8 CTAs, 4 rows/cluster, 2 CTAs/SM. Intra-warp split-K with
// shfl butterfly; zero __syncthreads in the loop; split hw cluster barriers.
// ============================================================================
struct __align__(16) RecSmem {
    float wc4[32][8][8][4];    // Wc h-part [kk][c>>2][kg][c&3]          32KB
    float hT[2][264 * 4];      // h, skewed rows of 16B [buf]           8.25KB
    float rhT[264 * 4];        // r*h, skewed                           4.1KB
};

__global__ __launch_bounds__(256, 2) __cluster_dims__(8, 1, 1)
void rec_kernel(const float* __restrict__ h0,
                const float* __restrict__ Wr,
                const float* __restrict__ Wz,
                const float* __restrict__ Wc,
                float* __restrict__ out)
{
    extern __shared__ char smem_raw[];
    RecSmem& S = *reinterpret_cast<RecSmem*>(smem_raw);

    const int tid = threadIdx.x;
    const int warp = tid >> 5, lane = tid & 31;
    const int j = (int)cluster_rank();       // 0..7
    const int b0 = (blockIdx.x >> 3) * 4;    // first batch row of cluster

    // roles
    const int c_local = warp * 4 + (lane & 3);   // output col within CTA, 0..31
    const int kg = lane >> 2;                    // split-K group, 0..7
    const int kb = kg * 32;
    const bool pusher = (lane < 16);
    const int rp = (lane >> 2) & 1;              // row-pair (pushers)
    const int pg = (lane >> 3) & 1;              // peer group (pushers)
    const int k_glob = j * 32 + c_local;
    const int kr_own = k_glob + j;               // skewed row of own col

    // ---- register weights for r and z gates (1 col x 32 k each) ----
    float w1r[32], w1z[32];
    {
        const int c = k_glob;
        #pragma unroll
        for (int kk = 0; kk < 32; kk++) {
            w1r[kk] = Wr[(size_t)(256 + kb + kk) * 256 + c];
            w1z[kk] = Wz[(size_t)(256 + kb + kk) * 256 + c];
        }
    }

    // ---- SMEM init: Wc tile (bank-friendly layout), h state (buffer 0) ----
    for (int idx = tid; idx < 8192; idx += 256) {
        int k = idx >> 5, c = idx & 31;
        S.wc4[k & 31][c >> 2][k >> 5][c & 3] =
            Wc[(size_t)(256 + k) * 256 + j * 32 + c];
    }
    for (int idx = tid; idx < 1024; idx += 256) {
        int k = idx >> 2, r = idx & 3;
        S.hT[0][(k + (k >> 5)) * 4 + r] = h0[(size_t)(b0 + r) * 256 + k];
    }
    __syncthreads();
    cluster_sync();   // peers' hT init visible before any remote op

    // ---- peer DSMEM addresses ----
    const uint32_t base = smem_u32(&S);
    uint32_t peer[8];
    #pragma unroll
    for (int rk = 0; rk < 8; rk++) peer[rk] = mapa_rank(base, (uint32_t)rk);
    const uint32_t off_h[2]  = { (uint32_t)(smem_u32(&S.hT[0][0]) - base),
                                 (uint32_t)(smem_u32(&S.hT[1][0]) - base) };
    const uint32_t off_rh    = (uint32_t)(smem_u32(&S.rhT[0]) - base);

    // ---- Gx address bases for pusher lanes ----
    const size_t bR0 = (size_t)(b0 + 2 * rp)     * TSTEPS * 768 + k_glob;
    const size_t bR1 = (size_t)(b0 + 2 * rp + 1) * TSTEPS * 768 + k_glob;

    // prologue: gR for step 0
    float gR0 = 0.f, gR1 = 0.f;
    if (pusher) { gR0 = g_Gx[bR0]; gR1 = g_Gx[bR1]; }

    #pragma unroll 1
    for (int t = 0; t < TSTEPS; t++) {
        const int buf = t & 1;

        // gZ/gC loads first: latency overlaps WAIT2 + GEMM_r..GEMM_z
        float gZ0 = 0.f, gZ1 = 0.f, gC0 = 0.f, gC1 = 0.f;
        if (pusher) {
            const size_t to = (size_t)t * 768;
            gZ0 = g_Gx[bR0 + to + 256]; gZ1 = g_Gx[bR1 + to + 256];
            gC0 = g_Gx[bR0 + to + 512]; gC1 = g_Gx[bR1 + to + 512];
        }

        // WAIT2: h(t) pushed by all peers at end of step t-1
        if (t > 0) cluster_wait();

        // -- GEMM_r: h @ Wh_r (skewed hT; per-iter row kb+kk+kg) --
        float r0l, r0h, r1l, r1h;
        {
            ull a0 = 0, a1 = 0;
            #pragma unroll
            for (int kk = 0; kk < 32; kk++) {
                ulonglong2 hp = *reinterpret_cast<const ulonglong2*>(
                    &S.hT[buf][(kb + kk + kg) * 4]);
                ull w2 = pack2(w1r[kk], w1r[kk]);
                fma2(a0, hp.x, w2); fma2(a1, hp.y, w2);
            }
            unpack2(a0, r0l, r0h); unpack2(a1, r1l, r1h);
            bfly_kg(r0l, r0h); bfly_kg(r1l, r1h);
        }

        // -- epi_r (pushers): sigmoid r, push r*h (4 peers each) --
        if (pusher) {
            float sl = rp ? r1l : r0l, sh = rp ? r1h : r0h;
            float v0 = fast_sigmoid(sl + gR0), v1 = fast_sigmoid(sh + gR1);
            ull h2 = *reinterpret_cast<const ull*>(&S.hT[buf][kr_own * 4 + 2 * rp]);
            float ha, hb; unpack2(h2, ha, hb);
            ull rh2 = pack2(v0 * ha, v1 * hb);
            uint32_t o = off_rh + (uint32_t)((kr_own * 4 + 2 * rp) * 4);
            #pragma unroll
            for (int p = 0; p < 4; p++) st_cluster_u64(peer[4 * pg + p] + o, rh2);
        }
        // ARRIVE1: rh pushes issued (release); propagation hides under GEMM_z
        cluster_arrive();

        // -- GEMM_z: h @ Wh_z (overlaps the r*h exchange + barrier) --
        float z0 = 0.f, z1 = 0.f;
        {
            ull a0 = 0, a1 = 0;
            #pragma unroll
            for (int kk = 0; kk < 32; kk++) {
                ulonglong2 hp = *reinterpret_cast<const ulonglong2*>(
                    &S.hT[buf][(kb + kk + kg) * 4]);
                ull w2 = pack2(w1z[kk], w1z[kk]);
                fma2(a0, hp.x, w2); fma2(a1, hp.y, w2);
            }
            float z0l, z0h, z1l, z1h;
            unpack2(a0, z0l, z0h); unpack2(a1, z1l, z1h);
            bfly_kg(z0l, z0h); bfly_kg(z1l, z1h);
            if (pusher) {   // z stays in registers until epi_c (same lane)
                float sl = rp ? z1l : z0l, sh = rp ? z1h : z0h;
                z0 = fast_sigmoid(sl + gZ0); z1 = fast_sigmoid(sh + gZ1);
            }
        }

        // issue gR(t+1) prefetch BEFORE the wait: in flight across WAIT1+GEMM_c
        float gRn0 = gR0, gRn1 = gR1;
        if (pusher) {
            const size_t tn = (size_t)((t + 1 < TSTEPS) ? t + 1 : t) * 768;
            gRn0 = g_Gx[bR0 + tn]; gRn1 = g_Gx[bR1 + tn];
        }

        // WAIT1: rhT complete from all peers (mostly satisfied already)
        cluster_wait();

        // -- GEMM_c: (r*h) @ Wh_c (Wc from bank-friendly SMEM) --
        float c0l, c0h, c1l, c1h;
        {
            ull a0 = 0, a1 = 0;
            #pragma unroll
            for (int kk = 0; kk < 32; kk++) {
                ulonglong2 hp = *reinterpret_cast<const ulonglong2*>(
                    &S.rhT[(kb + kk + kg) * 4]);
                float w = S.wc4[kk][c_local >> 2][kg][c_local & 3];
                ull w2 = pack2(w, w);
                fma2(a0, hp.x, w2); fma2(a1, hp.y, w2);
            }
            unpack2(a0, c0l, c0h); unpack2(a1, c1l, c1h);
            bfly_kg(c0l, c0h); bfly_kg(c1l, c1h);
        }

        // -- epi_c (pushers): candidate, h update, output, push h(t+1) --
        if (pusher) {
            float sl = rp ? c1l : c0l, sh = rp ? c1h : c0h;
            float cv0 = fast_tanh(sl + gC0), cv1 = fast_tanh(sh + gC1);
            ull h2 = *reinterpret_cast<const ull*>(&S.hT[buf][kr_own * 4 + 2 * rp]);
            float ha, hb; unpack2(h2, ha, hb);
            float hn0 = ha + z0 * (cv0 - ha);
            float hn1 = hb + z1 * (cv1 - hb);
            if (pg == 0) {
                out[((size_t)(b0 + 2 * rp) * TSTEPS + t) * 256 + k_glob] = hn0;
                out[((size_t)(b0 + 2 * rp + 1) * TSTEPS + t) * 256 + k_glob] = hn1;
            }
            ull hn2 = pack2(hn0, hn1);
            uint32_t o = off_h[buf ^ 1] + (uint32_t)((kr_own * 4 + 2 * rp) * 4);
            #pragma unroll
            for (int p = 0; p < 4; p++) st_cluster_u64(peer[4 * pg + p] + o, hn2);
        }
        // ARRIVE2: h(t+1) pushes issued; next iteration's wait consumes it
        cluster_arrive();

        gR0 = gRn0; gR1 = gRn1;
    }

    // consume the final ARRIVE2 so no CTA exits with peer pushes in flight
    cluster_wait();
}

extern "C" void kernel_launch(void* const* d_in, const int* in_sizes, int n_in,
                              void* d_out, int out_size) {
    const float* x  = (const float*)d_in[0];
    const float* h0 = (const float*)d_in[1];
    const float* Wr = (const float*)d_in[2];
    const float* br = (const float*)d_in[3];
    const float* Wz = (const float*)d_in[4];
    const float* bz = (const float*)d_in[5];
    const float* Wc = (const float*)d_in[6];
    const float* bc = (const float*)d_in[7];
    float* out = (float*)d_out;

    cudaFuncSetAttribute(proj_kernel, cudaFuncAttributeMaxDynamicSharedMemorySize,
                         PROJ_SMEM_BYTES);
    cudaFuncSetAttribute(rec_kernel, cudaFuncAttributeMaxDynamicSharedMemorySize,
                         (int)sizeof(RecSmem));

    proj_kernel<<<dim3(512, 12), 256, PROJ_SMEM_BYTES>>>(x, Wr, br, Wz, bz, Wc, bc);
    rec_kernel<<<256, 256, sizeof(RecSmem)>>>(h0, Wr, Wz, Wc, out);
}

// round 16
// speedup vs baseline: 1.2011x; 1.0396x over previous
#include <cuda_runtime.h>
#include <cstdint>
#include <cstddef>

#define TSTEPS 512
#define BATCH  128

// 192MB scratch for the input projection (static device array: allowed).
__device__ float g_Gx[(size_t)BATCH * TSTEPS * 768];

// ---- f32x2 helpers ----
typedef unsigned long long ull;
__device__ __forceinline__ ull pack2(float x, float y) {
    ull u; asm("mov.b64 %0, {%1,%2};" : "=l"(u) : "f"(x), "f"(y)); return u;
}
__device__ __forceinline__ void unpack2(ull u, float& x, float& y) {
    asm("mov.b64 {%0,%1}, %2;" : "=f"(x), "=f"(y) : "l"(u));
}
__device__ __forceinline__ void fma2(ull& d, ull a, ull b) {
    asm("fma.rn.f32x2 %0, %1, %2, %0;" : "+l"(d) : "l"(a), "l"(b));
}

// ---- cluster helpers ----
__device__ __forceinline__ uint32_t smem_u32(const void* p) {
    uint32_t a;
    asm("{ .reg .u64 t; cvta.to.shared.u64 t, %1; cvt.u32.u64 %0, t; }" : "=r"(a) : "l"(p));
    return a;
}
__device__ __forceinline__ uint32_t mapa_rank(uint32_t addr, uint32_t rank) {
    uint32_t r; asm("mapa.shared::cluster.u32 %0, %1, %2;" : "=r"(r) : "r"(addr), "r"(rank));
    return r;
}
__device__ __forceinline__ void st_cluster_u64(uint32_t addr, ull v) {
    asm volatile("st.shared::cluster.b64 [%0], %1;" :: "r"(addr), "l"(v));
}
__device__ __forceinline__ void cluster_arrive() {
    asm volatile("barrier.cluster.arrive.aligned;" ::: "memory");
}
__device__ __forceinline__ void cluster_wait() {
    asm volatile("barrier.cluster.wait.aligned;" ::: "memory");
}
__device__ __forceinline__ void cluster_sync() {
    cluster_arrive(); cluster_wait();
}
__device__ __forceinline__ uint32_t cluster_rank() {
    uint32_t r; asm("mov.u32 %0, %%cluster_ctarank;" : "=r"(r)); return r;
}

// fast activations
__device__ __forceinline__ float fast_sigmoid(float x) {
    return __fdividef(1.0f, 1.0f + __expf(-x));
}
__device__ __forceinline__ float fast_tanh(float x) {
    return 2.0f * __fdividef(1.0f, 1.0f + __expf(-2.0f * x)) - 1.0f;
}

// butterfly reduce a (lo,hi) pair over the kg dimension (lane bits 2,3,4)
__device__ __forceinline__ void bfly_kg(float& lo, float& hi) {
    lo += __shfl_xor_sync(0xffffffffu, lo, 4);
    hi += __shfl_xor_sync(0xffffffffu, hi, 4);
    lo += __shfl_xor_sync(0xffffffffu, lo, 8);
    hi += __shfl_xor_sync(0xffffffffu, hi, 8);
    lo += __shfl_xor_sync(0xffffffffu, lo, 16);
    hi += __shfl_xor_sync(0xffffffffu, hi, 16);
}

// ============================================================================
// Stage 1: Gx[m][gate*256+n] = x[m] @ W[:256] + b.  BM=128 BN=64 BK=32.
// R11 proj shape (the only one measured at ~531us) + ONE edit: W tile stored
// skewed (Ws[32][68], col index n + (n>>5)) so the lane pair (tx, tx+8) no
// longer collides on a bank. Load-side skew is a per-thread CONSTANT offset
// (tx*4 + (tx>>3)): zero extra inner-loop instructions, conflict-free.
// ============================================================================
__global__ __launch_bounds__(256) void proj_kernel(
    const float* __restrict__ x,
    const float* __restrict__ Wr, const float* __restrict__ br,
    const float* __restrict__ Wz, const float* __restrict__ bz,
    const float* __restrict__ Wc, const float* __restrict__ bc)
{
    const int mTile = blockIdx.x, nTile = blockIdx.y;
    const int gate = nTile >> 2, nGateBase = (nTile & 3) * 64;
    const float* W    = (gate == 0) ? Wr : ((gate == 1) ? Wz : Wc);
    const float* bias = (gate == 0) ? br : ((gate == 1) ? bz : bc);

    __shared__ float As[32][132];   // [k][m]
    __shared__ float Ws[32][68];    // [k][n_skewed]: col = n + (n>>5)

    const int tid = threadIdx.x;
    const int tx = tid & 15, ty = tid >> 4;
    const int mBase = mTile * 128;
    const int wcol = tx * 4 + (tx >> 3);   // skewed base column (constant)

    ull acc[4][4];
    #pragma unroll
    for (int i = 0; i < 4; i++)
        #pragma unroll
        for (int jj = 0; jj < 4; jj++) acc[i][jj] = 0ull;

    float bv[4];
    #pragma unroll
    for (int jj = 0; jj < 4; jj++) bv[jj] = bias[nGateBase + tx * 4 + jj];

    for (int k0 = 0; k0 < 256; k0 += 32) {
        __syncthreads();
        // A tile: 128 rows x 32 k = 1024 float4 slots
        #pragma unroll
        for (int q = 0; q < 4; q++) {
            int idx = tid + q * 256, row = idx >> 3, c4 = idx & 7;
            float4 v = *reinterpret_cast<const float4*>(
                &x[(size_t)(mBase + row) * 256 + k0 + c4 * 4]);
            As[c4 * 4 + 0][row] = v.x; As[c4 * 4 + 1][row] = v.y;
            As[c4 * 4 + 2][row] = v.z; As[c4 * 4 + 3][row] = v.w;
        }
        // W tile: 32 k x 64 n, stored with skew (scalar stores; n4..n4+3
        // share one skew region since n4 is a multiple of 4)
        #pragma unroll
        for (int q = 0; q < 2; q++) {
            int s = tid + q * 256;
            int k = s >> 4, n4 = (s & 15) * 4;
            float4 v = *reinterpret_cast<const float4*>(
                &W[(size_t)(k0 + k) * 256 + nGateBase + n4]);
            int sc = n4 + (n4 >> 5);
            Ws[k][sc + 0] = v.x; Ws[k][sc + 1] = v.y;
            Ws[k][sc + 2] = v.z; Ws[k][sc + 3] = v.w;
        }
        __syncthreads();

        #pragma unroll
        for (int k = 0; k < 32; k++) {
            const ull* ap = reinterpret_cast<const ull*>(&As[k][ty * 8]);
            ull a0 = ap[0], a1 = ap[1], a2 = ap[2], a3 = ap[3];
            #pragma unroll
            for (int jj = 0; jj < 4; jj++) {
                float w = Ws[k][wcol + jj];
                ull w2 = pack2(w, w);
                fma2(acc[0][jj], a0, w2); fma2(acc[1][jj], a1, w2);
                fma2(acc[2][jj], a2, w2); fma2(acc[3][jj], a3, w2);
            }
        }
    }

    const int nOut = gate * 256 + nGateBase + tx * 4;
    #pragma unroll
    for (int rp = 0; rp < 4; rp++) {
        float r0[4], r1[4];
        #pragma unroll
        for (int jj = 0; jj < 4; jj++) {
            unpack2(acc[rp][jj], r0[jj], r1[jj]);
            r0[jj] += bv[jj]; r1[jj] += bv[jj];
        }
        int m0 = mBase + ty * 8 + rp * 2;
        *reinterpret_cast<float4*>(&g_Gx[(size_t)m0 * 768 + nOut]) =
            make_float4(r0[0], r0[1], r0[2], r0[3]);
        *reinterpret_cast<float4*>(&g_Gx[(size_t)(m0 + 1) * 768 + nOut]) =
            make_float4(r1[0], r1[1], r1[2], r1[3]);
    }
}

// ============================================================================
// Stage 2: recurrence — BYTE-IDENTICAL to R11/R13/R15 (rec 2053-2058us).
// 32 clusters x 8 CTAs, 4 rows/cluster, 2 CTAs/SM. Intra-warp split-K with
// shfl butterfly; zero __syncthreads in the loop; split hw cluster barriers.
// ============================================================================
struct __align__(16) RecSmem {
    float wc4[32][8][8][4];    // Wc h-part [kk][c>>2][kg][c&3]          32KB
    float hT[2][264 * 4];      // h, skewed rows of 16B [buf]           8.25KB
    float rhT[264 * 4];        // r*h, skewed                           4.1KB
};

__global__ __launch_bounds__(256, 2) __cluster_dims__(8, 1, 1)
void rec_kernel(const float* __restrict__ h0,
                const float* __restrict__ Wr,
                const float* __restrict__ Wz,
                const float* __restrict__ Wc,
                float* __restrict__ out)
{
    extern __shared__ char smem_raw[];
    RecSmem& S = *reinterpret_cast<RecSmem*>(smem_raw);

    const int tid = threadIdx.x;
    const int warp = tid >> 5, lane = tid & 31;
    const int j = (int)cluster_rank();       // 0..7
    const int b0 = (blockIdx.x >> 3) * 4;    // first batch row of cluster

    // roles
    const int c_local = warp * 4 + (lane & 3);   // output col within CTA, 0..31
    const int kg = lane >> 2;                    // split-K group, 0..7
    const int kb = kg * 32;
    const bool pusher = (lane < 16);
    const int rp = (lane >> 2) & 1;              // row-pair (pushers)
    const int pg = (lane >> 3) & 1;              // peer group (pushers)
    const int k_glob = j * 32 + c_local;
    const int kr_own = k_glob + j;               // skewed row of own col

    // ---- register weights for r and z gates (1 col x 32 k each) ----
    float w1r[32], w1z[32];
    {
        const int c = k_glob;
        #pragma unroll
        for (int kk = 0; kk < 32; kk++) {
            w1r[kk] = Wr[(size_t)(256 + kb + kk) * 256 + c];
            w1z[kk] = Wz[(size_t)(256 + kb + kk) * 256 + c];
        }
    }

    // ---- SMEM init: Wc tile (bank-friendly layout), h state (buffer 0) ----
    for (int idx = tid; idx < 8192; idx += 256) {
        int k = idx >> 5, c = idx & 31;
        S.wc4[k & 31][c >> 2][k >> 5][c & 3] =
            Wc[(size_t)(256 + k) * 256 + j * 32 + c];
    }
    for (int idx = tid; idx < 1024; idx += 256) {
        int k = idx >> 2, r = idx & 3;
        S.hT[0][(k + (k >> 5)) * 4 + r] = h0[(size_t)(b0 + r) * 256 + k];
    }
    __syncthreads();
    cluster_sync();   // peers' hT init visible before any remote op

    // ---- peer DSMEM addresses ----
    const uint32_t base = smem_u32(&S);
    uint32_t peer[8];
    #pragma unroll
    for (int rk = 0; rk < 8; rk++) peer[rk] = mapa_rank(base, (uint32_t)rk);
    const uint32_t off_h[2]  = { (uint32_t)(smem_u32(&S.hT[0][0]) - base),
                                 (uint32_t)(smem_u32(&S.hT[1][0]) - base) };
    const uint32_t off_rh    = (uint32_t)(smem_u32(&S.rhT[0]) - base);

    // ---- Gx address bases for pusher lanes ----
    const size_t bR0 = (size_t)(b0 + 2 * rp)     * TSTEPS * 768 + k_glob;
    const size_t bR1 = (size_t)(b0 + 2 * rp + 1) * TSTEPS * 768 + k_glob;

    // prologue: gR for step 0
    float gR0 = 0.f, gR1 = 0.f;
    if (pusher) { gR0 = g_Gx[bR0]; gR1 = g_Gx[bR1]; }

    #pragma unroll 1
    for (int t = 0; t < TSTEPS; t++) {
        const int buf = t & 1;

        // gZ/gC loads first: latency overlaps WAIT2 + GEMM_r..GEMM_z
        float gZ0 = 0.f, gZ1 = 0.f, gC0 = 0.f, gC1 = 0.f;
        if (pusher) {
            const size_t to = (size_t)t * 768;
            gZ0 = g_Gx[bR0 + to + 256]; gZ1 = g_Gx[bR1 + to + 256];
            gC0 = g_Gx[bR0 + to + 512]; gC1 = g_Gx[bR1 + to + 512];
        }

        // WAIT2: h(t) pushed by all peers at end of step t-1
        if (t > 0) cluster_wait();

        // -- GEMM_r: h @ Wh_r (skewed hT; per-iter row kb+kk+kg) --
        float r0l, r0h, r1l, r1h;
        {
            ull a0 = 0, a1 = 0;
            #pragma unroll
            for (int kk = 0; kk < 32; kk++) {
                ulonglong2 hp = *reinterpret_cast<const ulonglong2*>(
                    &S.hT[buf][(kb + kk + kg) * 4]);
                ull w2 = pack2(w1r[kk], w1r[kk]);
                fma2(a0, hp.x, w2); fma2(a1, hp.y, w2);
            }
            unpack2(a0, r0l, r0h); unpack2(a1, r1l, r1h);
            bfly_kg(r0l, r0h); bfly_kg(r1l, r1h);
        }

        // -- epi_r (pushers): sigmoid r, push r*h (4 peers each) --
        if (pusher) {
            float sl = rp ? r1l : r0l, sh = rp ? r1h : r0h;
            float v0 = fast_sigmoid(sl + gR0), v1 = fast_sigmoid(sh + gR1);
            ull h2 = *reinterpret_cast<const ull*>(&S.hT[buf][kr_own * 4 + 2 * rp]);
            float ha, hb; unpack2(h2, ha, hb);
            ull rh2 = pack2(v0 * ha, v1 * hb);
            uint32_t o = off_rh + (uint32_t)((kr_own * 4 + 2 * rp) * 4);
            #pragma unroll
            for (int p = 0; p < 4; p++) st_cluster_u64(peer[4 * pg + p] + o, rh2);
        }
        // ARRIVE1: rh pushes issued (release); propagation hides under GEMM_z
        cluster_arrive();

        // -- GEMM_z: h @ Wh_z (overlaps the r*h exchange + barrier) --
        float z0 = 0.f, z1 = 0.f;
        {
            ull a0 = 0, a1 = 0;
            #pragma unroll
            for (int kk = 0; kk < 32; kk++) {
                ulonglong2 hp = *reinterpret_cast<const ulonglong2*>(
                    &S.hT[buf][(kb + kk + kg) * 4]);
                ull w2 = pack2(w1z[kk], w1z[kk]);
                fma2(a0, hp.x, w2); fma2(a1, hp.y, w2);
            }
            float z0l, z0h, z1l, z1h;
            unpack2(a0, z0l, z0h); unpack2(a1, z1l, z1h);
            bfly_kg(z0l, z0h); bfly_kg(z1l, z1h);
            if (pusher) {   // z stays in registers until epi_c (same lane)
                float sl = rp ? z1l : z0l, sh = rp ? z1h : z0h;
                z0 = fast_sigmoid(sl + gZ0); z1 = fast_sigmoid(sh + gZ1);
            }
        }

        // issue gR(t+1) prefetch BEFORE the wait: in flight across WAIT1+GEMM_c
        float gRn0 = gR0, gRn1 = gR1;
        if (pusher) {
            const size_t tn = (size_t)((t + 1 < TSTEPS) ? t + 1 : t) * 768;
            gRn0 = g_Gx[bR0 + tn]; gRn1 = g_Gx[bR1 + tn];
        }

        // WAIT1: rhT complete from all peers (mostly satisfied already)
        cluster_wait();

        // -- GEMM_c: (r*h) @ Wh_c (Wc from bank-friendly SMEM) --
        float c0l, c0h, c1l, c1h;
        {
            ull a0 = 0, a1 = 0;
            #pragma unroll
            for (int kk = 0; kk < 32; kk++) {
                ulonglong2 hp = *reinterpret_cast<const ulonglong2*>(
                    &S.rhT[(kb + kk + kg) * 4]);
                float w = S.wc4[kk][c_local >> 2][kg][c_local & 3];
                ull w2 = pack2(w, w);
                fma2(a0, hp.x, w2); fma2(a1, hp.y, w2);
            }
            unpack2(a0, c0l, c0h); unpack2(a1, c1l, c1h);
            bfly_kg(c0l, c0h); bfly_kg(c1l, c1h);
        }

        // -- epi_c (pushers): candidate, h update, output, push h(t+1) --
        if (pusher) {
            float sl = rp ? c1l : c0l, sh = rp ? c1h : c0h;
            float cv0 = fast_tanh(sl + gC0), cv1 = fast_tanh(sh + gC1);
            ull h2 = *reinterpret_cast<const ull*>(&S.hT[buf][kr_own * 4 + 2 * rp]);
            float ha, hb; unpack2(h2, ha, hb);
            float hn0 = ha + z0 * (cv0 - ha);
            float hn1 = hb + z1 * (cv1 - hb);
            if (pg == 0) {
                out[((size_t)(b0 + 2 * rp) * TSTEPS + t) * 256 + k_glob] = hn0;
                out[((size_t)(b0 + 2 * rp + 1) * TSTEPS + t) * 256 + k_glob] = hn1;
            }
            ull hn2 = pack2(hn0, hn1);
            uint32_t o = off_h[buf ^ 1] + (uint32_t)((kr_own * 4 + 2 * rp) * 4);
            #pragma unroll
            for (int p = 0; p < 4; p++) st_cluster_u64(peer[4 * pg + p] + o, hn2);
        }
        // ARRIVE2: h(t+1) pushes issued; next iteration's wait consumes it
        cluster_arrive();

        gR0 = gRn0; gR1 = gRn1;
    }

    // consume the final ARRIVE2 so no CTA exits with peer pushes in flight
    cluster_wait();
}

extern "C" void kernel_launch(void* const* d_in, const int* in_sizes, int n_in,
                              void* d_out, int out_size) {
    const float* x  = (const float*)d_in[0];
    const float* h0 = (const float*)d_in[1];
    const float* Wr = (const float*)d_in[2];
    const float* br = (const float*)d_in[3];
    const float* Wz = (const float*)d_in[4];
    const float* bz = (const float*)d_in[5];
    const float* Wc = (const float*)d_in[6];
    const float* bc = (const float*)d_in[7];
    float* out = (float*)d_out;

    cudaFuncSetAttribute(rec_kernel, cudaFuncAttributeMaxDynamicSharedMemorySize,
                         (int)sizeof(RecSmem));

    proj_kernel<<<dim3(512, 12), 256>>>(x, Wr, br, Wz, bz, Wc, bc);
    rec_kernel<<<256, 256, sizeof(RecSmem)>>>(h0, Wr, Wz, Wc, out);
}

// round 17
// speedup vs baseline: 1.2190x; 1.0149x over previous
#include <cuda_runtime.h>
#include <cstdint>
#include <cstddef>

#define TSTEPS 512
#define BATCH  128

// 192MB scratch for the input projection (static device array: allowed).
__device__ float g_Gx[(size_t)BATCH * TSTEPS * 768];

// ---- f32x2 helpers ----
typedef unsigned long long ull;
__device__ __forceinline__ ull pack2(float x, float y) {
    ull u; asm("mov.b64 %0, {%1,%2};" : "=l"(u) : "f"(x), "f"(y)); return u;
}
__device__ __forceinline__ void unpack2(ull u, float& x, float& y) {
    asm("mov.b64 {%0,%1}, %2;" : "=f"(x), "=f"(y) : "l"(u));
}
__device__ __forceinline__ void fma2(ull& d, ull a, ull b) {
    asm("fma.rn.f32x2 %0, %1, %2, %0;" : "+l"(d) : "l"(a), "l"(b));
}

// ---- cluster helpers ----
__device__ __forceinline__ uint32_t smem_u32(const void* p) {
    uint32_t a;
    asm("{ .reg .u64 t; cvta.to.shared.u64 t, %1; cvt.u32.u64 %0, t; }" : "=r"(a) : "l"(p));
    return a;
}
__device__ __forceinline__ uint32_t mapa_rank(uint32_t addr, uint32_t rank) {
    uint32_t r; asm("mapa.shared::cluster.u32 %0, %1, %2;" : "=r"(r) : "r"(addr), "r"(rank));
    return r;
}
__device__ __forceinline__ void st_cluster_u64(uint32_t addr, ull v) {
    asm volatile("st.shared::cluster.b64 [%0], %1;" :: "r"(addr), "l"(v));
}
__device__ __forceinline__ void cluster_arrive() {
    asm volatile("barrier.cluster.arrive.aligned;" ::: "memory");
}
__device__ __forceinline__ void cluster_wait() {
    asm volatile("barrier.cluster.wait.aligned;" ::: "memory");
}
__device__ __forceinline__ void cluster_sync() {
    cluster_arrive(); cluster_wait();
}
__device__ __forceinline__ uint32_t cluster_rank() {
    uint32_t r; asm("mov.u32 %0, %%cluster_ctarank;" : "=r"(r)); return r;
}

// fast activations
__device__ __forceinline__ float fast_sigmoid(float x) {
    return __fdividef(1.0f, 1.0f + __expf(-x));
}
__device__ __forceinline__ float fast_tanh(float x) {
    return 2.0f * __fdividef(1.0f, 1.0f + __expf(-2.0f * x)) - 1.0f;
}

// butterfly reduce a (lo,hi) pair over the kg dimension (lane bits 2,3,4)
__device__ __forceinline__ void bfly_kg(float& lo, float& hi) {
    lo += __shfl_xor_sync(0xffffffffu, lo, 4);
    hi += __shfl_xor_sync(0xffffffffu, hi, 4);
    lo += __shfl_xor_sync(0xffffffffu, lo, 8);
    hi += __shfl_xor_sync(0xffffffffu, hi, 8);
    lo += __shfl_xor_sync(0xffffffffu, lo, 16);
    hi += __shfl_xor_sync(0xffffffffu, hi, 16);
}

// ============================================================================
// Stage 1: Gx[m][gate*256+n] = x[m] @ W[:256] + b.  BM=128 BN=64 BK=32.
// Plain single-buffer tiles: the only proj shape measured at ~531us.
// ============================================================================
__global__ __launch_bounds__(256) void proj_kernel(
    const float* __restrict__ x,
    const float* __restrict__ Wr, const float* __restrict__ br,
    const float* __restrict__ Wz, const float* __restrict__ bz,
    const float* __restrict__ Wc, const float* __restrict__ bc)
{
    const int mTile = blockIdx.x, nTile = blockIdx.y;
    const int gate = nTile >> 2, nGateBase = (nTile & 3) * 64;
    const float* W    = (gate == 0) ? Wr : ((gate == 1) ? Wz : Wc);
    const float* bias = (gate == 0) ? br : ((gate == 1) ? bz : bc);

    __shared__ float As[32][132];   // [k][m]
    __shared__ float Ws[32][64];    // [k][n]

    const int tid = threadIdx.x;
    const int tx = tid & 15, ty = tid >> 4;
    const int mBase = mTile * 128;

    ull acc[4][4];
    #pragma unroll
    for (int i = 0; i < 4; i++)
        #pragma unroll
        for (int jj = 0; jj < 4; jj++) acc[i][jj] = 0ull;

    float bv[4];
    #pragma unroll
    for (int jj = 0; jj < 4; jj++) bv[jj] = bias[nGateBase + tx * 4 + jj];

    for (int k0 = 0; k0 < 256; k0 += 32) {
        __syncthreads();
        // A tile: 128 rows x 32 k = 1024 float4 slots
        #pragma unroll
        for (int q = 0; q < 4; q++) {
            int idx = tid + q * 256, row = idx >> 3, c4 = idx & 7;
            float4 v = *reinterpret_cast<const float4*>(
                &x[(size_t)(mBase + row) * 256 + k0 + c4 * 4]);
            As[c4 * 4 + 0][row] = v.x; As[c4 * 4 + 1][row] = v.y;
            As[c4 * 4 + 2][row] = v.z; As[c4 * 4 + 3][row] = v.w;
        }
        // W tile: 32 k x 64 n = 512 float4 slots
        #pragma unroll
        for (int q = 0; q < 2; q++) {
            int s = tid + q * 256;
            int k = s >> 4, n4 = (s & 15) * 4;
            *reinterpret_cast<float4*>(&Ws[k][n4]) =
                *reinterpret_cast<const float4*>(&W[(size_t)(k0 + k) * 256 + nGateBase + n4]);
        }
        __syncthreads();

        #pragma unroll
        for (int k = 0; k < 32; k++) {
            const ull* ap = reinterpret_cast<const ull*>(&As[k][ty * 8]);
            ull a0 = ap[0], a1 = ap[1], a2 = ap[2], a3 = ap[3];
            #pragma unroll
            for (int jj = 0; jj < 4; jj++) {
                float w = Ws[k][tx * 4 + jj];
                ull w2 = pack2(w, w);
                fma2(acc[0][jj], a0, w2); fma2(acc[1][jj], a1, w2);
                fma2(acc[2][jj], a2, w2); fma2(acc[3][jj], a3, w2);
            }
        }
    }

    const int nOut = gate * 256 + nGateBase + tx * 4;
    #pragma unroll
    for (int rp = 0; rp < 4; rp++) {
        float r0[4], r1[4];
        #pragma unroll
        for (int jj = 0; jj < 4; jj++) {
            unpack2(acc[rp][jj], r0[jj], r1[jj]);
            r0[jj] += bv[jj]; r1[jj] += bv[jj];
        }
        int m0 = mBase + ty * 8 + rp * 2;
        *reinterpret_cast<float4*>(&g_Gx[(size_t)m0 * 768 + nOut]) =
            make_float4(r0[0], r0[1], r0[2], r0[3]);
        *reinterpret_cast<float4*>(&g_Gx[(size_t)(m0 + 1) * 768 + nOut]) =
            make_float4(r1[0], r1[1], r1[2], r1[3]);
    }
}

// ============================================================================
// Stage 2: recurrence — R11 exactly (rec 2053-2058us, reproduced 4x).
// 32 clusters x 8 CTAs, 4 rows/cluster, 2 CTAs/SM. Intra-warp split-K with
// shfl butterfly; zero __syncthreads in the loop; split hw cluster barriers.
// ============================================================================
struct __align__(16) RecSmem {
    float wc4[32][8][8][4];    // Wc h-part [kk][c>>2][kg][c&3]          32KB
    float hT[2][264 * 4];      // h, skewed rows of 16B [buf]           8.25KB
    float rhT[264 * 4];        // r*h, skewed                           4.1KB
};

__global__ __launch_bounds__(256, 2) __cluster_dims__(8, 1, 1)
void rec_kernel(const float* __restrict__ h0,
                const float* __restrict__ Wr,
                const float* __restrict__ Wz,
                const float* __restrict__ Wc,
                float* __restrict__ out)
{
    extern __shared__ char smem_raw[];
    RecSmem& S = *reinterpret_cast<RecSmem*>(smem_raw);

    const int tid = threadIdx.x;
    const int warp = tid >> 5, lane = tid & 31;
    const int j = (int)cluster_rank();       // 0..7
    const int b0 = (blockIdx.x >> 3) * 4;    // first batch row of cluster

    // roles
    const int c_local = warp * 4 + (lane & 3);   // output col within CTA, 0..31
    const int kg = lane >> 2;                    // split-K group, 0..7
    const int kb = kg * 32;
    const bool pusher = (lane < 16);
    const int rp = (lane >> 2) & 1;              // row-pair (pushers)
    const int pg = (lane >> 3) & 1;              // peer group (pushers)
    const int k_glob = j * 32 + c_local;
    const int kr_own = k_glob + j;               // skewed row of own col

    // ---- register weights for r and z gates (1 col x 32 k each) ----
    float w1r[32], w1z[32];
    {
        const int c = k_glob;
        #pragma unroll
        for (int kk = 0; kk < 32; kk++) {
            w1r[kk] = Wr[(size_t)(256 + kb + kk) * 256 + c];
            w1z[kk] = Wz[(size_t)(256 + kb + kk) * 256 + c];
        }
    }

    // ---- SMEM init: Wc tile (bank-friendly layout), h state (buffer 0) ----
    for (int idx = tid; idx < 8192; idx += 256) {
        int k = idx >> 5, c = idx & 31;
        S.wc4[k & 31][c >> 2][k >> 5][c & 3] =
            Wc[(size_t)(256 + k) * 256 + j * 32 + c];
    }
    for (int idx = tid; idx < 1024; idx += 256) {
        int k = idx >> 2, r = idx & 3;
        S.hT[0][(k + (k >> 5)) * 4 + r] = h0[(size_t)(b0 + r) * 256 + k];
    }
    __syncthreads();
    cluster_sync();   // peers' hT init visible before any remote op

    // ---- peer DSMEM addresses ----
    const uint32_t base = smem_u32(&S);
    uint32_t peer[8];
    #pragma unroll
    for (int rk = 0; rk < 8; rk++) peer[rk] = mapa_rank(base, (uint32_t)rk);
    const uint32_t off_h[2]  = { (uint32_t)(smem_u32(&S.hT[0][0]) - base),
                                 (uint32_t)(smem_u32(&S.hT[1][0]) - base) };
    const uint32_t off_rh    = (uint32_t)(smem_u32(&S.rhT[0]) - base);

    // ---- Gx address bases for pusher lanes ----
    const size_t bR0 = (size_t)(b0 + 2 * rp)     * TSTEPS * 768 + k_glob;
    const size_t bR1 = (size_t)(b0 + 2 * rp + 1) * TSTEPS * 768 + k_glob;

    // prologue: gR for step 0
    float gR0 = 0.f, gR1 = 0.f;
    if (pusher) { gR0 = g_Gx[bR0]; gR1 = g_Gx[bR1]; }

    #pragma unroll 1
    for (int t = 0; t < TSTEPS; t++) {
        const int buf = t & 1;

        // gZ/gC loads first: latency overlaps WAIT2 + GEMM_r..GEMM_z
        float gZ0 = 0.f, gZ1 = 0.f, gC0 = 0.f, gC1 = 0.f;
        if (pusher) {
            const size_t to = (size_t)t * 768;
            gZ0 = g_Gx[bR0 + to + 256]; gZ1 = g_Gx[bR1 + to + 256];
            gC0 = g_Gx[bR0 + to + 512]; gC1 = g_Gx[bR1 + to + 512];
        }

        // WAIT2: h(t) pushed by all peers at end of step t-1
        if (t > 0) cluster_wait();

        // -- GEMM_r: h @ Wh_r (skewed hT; per-iter row kb+kk+kg) --
        float r0l, r0h, r1l, r1h;
        {
            ull a0 = 0, a1 = 0;
            #pragma unroll
            for (int kk = 0; kk < 32; kk++) {
                ulonglong2 hp = *reinterpret_cast<const ulonglong2*>(
                    &S.hT[buf][(kb + kk + kg) * 4]);
                ull w2 = pack2(w1r[kk], w1r[kk]);
                fma2(a0, hp.x, w2); fma2(a1, hp.y, w2);
            }
            unpack2(a0, r0l, r0h); unpack2(a1, r1l, r1h);
            bfly_kg(r0l, r0h); bfly_kg(r1l, r1h);
        }

        // -- epi_r (pushers): sigmoid r, push r*h (4 peers each) --
        if (pusher) {
            float sl = rp ? r1l : r0l, sh = rp ? r1h : r0h;
            float v0 = fast_sigmoid(sl + gR0), v1 = fast_sigmoid(sh + gR1);
            ull h2 = *reinterpret_cast<const ull*>(&S.hT[buf][kr_own * 4 + 2 * rp]);
            float ha, hb; unpack2(h2, ha, hb);
            ull rh2 = pack2(v0 * ha, v1 * hb);
            uint32_t o = off_rh + (uint32_t)((kr_own * 4 + 2 * rp) * 4);
            #pragma unroll
            for (int p = 0; p < 4; p++) st_cluster_u64(peer[4 * pg + p] + o, rh2);
        }
        // ARRIVE1: rh pushes issued (release); propagation hides under GEMM_z
        cluster_arrive();

        // -- GEMM_z: h @ Wh_z (overlaps the r*h exchange + barrier) --
        float z0 = 0.f, z1 = 0.f;
        {
            ull a0 = 0, a1 = 0;
            #pragma unroll
            for (int kk = 0; kk < 32; kk++) {
                ulonglong2 hp = *reinterpret_cast<const ulonglong2*>(
                    &S.hT[buf][(kb + kk + kg) * 4]);
                ull w2 = pack2(w1z[kk], w1z[kk]);
                fma2(a0, hp.x, w2); fma2(a1, hp.y, w2);
            }
            float z0l, z0h, z1l, z1h;
            unpack2(a0, z0l, z0h); unpack2(a1, z1l, z1h);
            bfly_kg(z0l, z0h); bfly_kg(z1l, z1h);
            if (pusher) {   // z stays in registers until epi_c (same lane)
                float sl = rp ? z1l : z0l, sh = rp ? z1h : z0h;
                z0 = fast_sigmoid(sl + gZ0); z1 = fast_sigmoid(sh + gZ1);
            }
        }

        // issue gR(t+1) prefetch BEFORE the wait: in flight across WAIT1+GEMM_c
        float gRn0 = gR0, gRn1 = gR1;
        if (pusher) {
            const size_t tn = (size_t)((t + 1 < TSTEPS) ? t + 1 : t) * 768;
            gRn0 = g_Gx[bR0 + tn]; gRn1 = g_Gx[bR1 + tn];
        }

        // WAIT1: rhT complete from all peers (mostly satisfied already)
        cluster_wait();

        // -- GEMM_c: (r*h) @ Wh_c (Wc from bank-friendly SMEM) --
        float c0l, c0h, c1l, c1h;
        {
            ull a0 = 0, a1 = 0;
            #pragma unroll
            for (int kk = 0; kk < 32; kk++) {
                ulonglong2 hp = *reinterpret_cast<const ulonglong2*>(
                    &S.rhT[(kb + kk + kg) * 4]);
                float w = S.wc4[kk][c_local >> 2][kg][c_local & 3];
                ull w2 = pack2(w, w);
                fma2(a0, hp.x, w2); fma2(a1, hp.y, w2);
            }
            unpack2(a0, c0l, c0h); unpack2(a1, c1l, c1h);
            bfly_kg(c0l, c0h); bfly_kg(c1l, c1h);
        }

        // -- epi_c (pushers): candidate, h update, output, push h(t+1) --
        if (pusher) {
            float sl = rp ? c1l : c0l, sh = rp ? c1h : c0h;
            float cv0 = fast_tanh(sl + gC0), cv1 = fast_tanh(sh + gC1);
            ull h2 = *reinterpret_cast<const ull*>(&S.hT[buf][kr_own * 4 + 2 * rp]);
            float ha, hb; unpack2(h2, ha, hb);
            float hn0 = ha + z0 * (cv0 - ha);
            float hn1 = hb + z1 * (cv1 - hb);
            if (pg == 0) {
                out[((size_t)(b0 + 2 * rp) * TSTEPS + t) * 256 + k_glob] = hn0;
                out[((size_t)(b0 + 2 * rp + 1) * TSTEPS + t) * 256 + k_glob] = hn1;
            }
            ull hn2 = pack2(hn0, hn1);
            uint32_t o = off_h[buf ^ 1] + (uint32_t)((kr_own * 4 + 2 * rp) * 4);
            #pragma unroll
            for (int p = 0; p < 4; p++) st_cluster_u64(peer[4 * pg + p] + o, hn2);
        }
        // ARRIVE2: h(t+1) pushes issued; next iteration's wait consumes it
        cluster_arrive();

        gR0 = gRn0; gR1 = gRn1;
    }

    // consume the final ARRIVE2 so no CTA exits with peer pushes in flight
    cluster_wait();
}

extern "C" void kernel_launch(void* const* d_in, const int* in_sizes, int n_in,
                              void* d_out, int out_size) {
    const float* x  = (const float*)d_in[0];
    const float* h0 = (const float*)d_in[1];
    const float* Wr = (const float*)d_in[2];
    const float* br = (const float*)d_in[3];
    const float* Wz = (const float*)d_in[4];
    const float* bz = (const float*)d_in[5];
    const float* Wc = (const float*)d_in[6];
    const float* bc = (const float*)d_in[7];
    float* out = (float*)d_out;

    cudaFuncSetAttribute(rec_kernel, cudaFuncAttributeMaxDynamicSharedMemorySize,
                         (int)sizeof(RecSmem));

    proj_kernel<<<dim3(512, 12), 256>>>(x, Wr, br, Wz, bz, Wc, bc);
    rec_kernel<<<256, 256, sizeof(RecSmem)>>>(h0, Wr, Wz, Wc, out);
}